// round 4
// baseline (speedup 1.0000x reference)
#include <cuda_runtime.h>

#define SEQL   2048
#define BATCH  2
#define DMODEL 1024
#define NHEAD  16
#define DK     64
#define NT     (SEQL*BATCH)      // 4096 token rows
#define BH     (BATCH*NHEAD)     // 32
#define QSCALE 0.125f            // DK^-0.5

// Scratch (static device globals — no runtime allocation allowed)
__device__ float g_qT[BH*DK*SEQL];     // [bh][dk][l]  (transposed for flash)
__device__ float g_kT[BH*DK*SEQL];     // [bh][dk][s]
__device__ float g_v [BH*SEQL*DK];     // [bh][s][dk]
__device__ float g_attn[NT*DMODEL];    // merged heads [t][d]

// ---------------------------------------------------------------------------
// Generic GEMM: val[t][d] = (sum_i A[t][i] * W[d][i] + bias[d]) * scale
// 128x128 tile, 256 threads, 8x8 per-thread micro-tile (2x2 quadrants of 4x4).
// MODE 0: store head-split TRANSPOSED  [bh][dk][l]   (Q, K)
// MODE 1: store head-split natural     [bh][s][dk]   (V)
// MODE 2: store plain                  [t][d]        (final output)
// ---------------------------------------------------------------------------
template<int MODE>
__global__ void __launch_bounds__(256, 2) gemm_k(const float* __restrict__ A,
                                                 const float* __restrict__ W,
                                                 const float* __restrict__ bias,
                                                 float* __restrict__ out,
                                                 float scale)
{
    __shared__ __align__(16) float AsT[16][132];   // [k][t_local], pad->132 (528B rows, 16B aligned)
    __shared__ __align__(16) float WsT[16][132];   // [k][d_local]

    const int tid = threadIdx.x;
    const int ty = tid >> 4;      // 0..15 -> row quadrants
    const int tx = tid & 15;      // 0..15 -> col quadrants
    const int t0 = blockIdx.y * 128;
    const int d0 = blockIdx.x * 128;

    float acc[8][8];
    #pragma unroll
    for (int r = 0; r < 8; r++)
        #pragma unroll
        for (int c = 0; c < 8; c++) acc[r][c] = 0.f;

    for (int kc = 0; kc < DMODEL; kc += 16) {
        // Load + transpose 128x16 tiles of A and W into smem
        #pragma unroll
        for (int i = 0; i < 2; i++) {
            int f   = tid + i * 256;
            int row = f >> 2;            // 0..127
            int q4  = (f & 3) << 2;      // 0,4,8,12
            float4 av = *(const float4*)(A + (t0 + row) * DMODEL + kc + q4);
            AsT[q4+0][row] = av.x; AsT[q4+1][row] = av.y;
            AsT[q4+2][row] = av.z; AsT[q4+3][row] = av.w;
            float4 wv = *(const float4*)(W + (d0 + row) * DMODEL + kc + q4);
            WsT[q4+0][row] = wv.x; WsT[q4+1][row] = wv.y;
            WsT[q4+2][row] = wv.z; WsT[q4+3][row] = wv.w;
        }
        __syncthreads();

        #pragma unroll
        for (int i = 0; i < 16; i++) {
            float4 a0 = *(const float4*)&AsT[i][4*ty];
            float4 a1 = *(const float4*)&AsT[i][64 + 4*ty];
            float4 w0 = *(const float4*)&WsT[i][4*tx];
            float4 w1 = *(const float4*)&WsT[i][64 + 4*tx];
            float av[8] = {a0.x,a0.y,a0.z,a0.w,a1.x,a1.y,a1.z,a1.w};
            float wv[8] = {w0.x,w0.y,w0.z,w0.w,w1.x,w1.y,w1.z,w1.w};
            #pragma unroll
            for (int r = 0; r < 8; r++)
                #pragma unroll
                for (int c = 0; c < 8; c++)
                    acc[r][c] += av[r] * wv[c];
        }
        __syncthreads();
    }

    // Epilogue
    #pragma unroll
    for (int r = 0; r < 8; r++) {
        int t = t0 + ((r < 4) ? 4*ty + r : 60 + 4*ty + r);
        #pragma unroll
        for (int c = 0; c < 8; c++) {
            int d = d0 + ((c < 4) ? 4*tx + c : 60 + 4*tx + c);
            float val = (acc[r][c] + bias[d]) * scale;
            if (MODE == 0) {
                int l = t >> 1, b = t & 1, h = d >> 6, dk = d & 63;
                out[(((b << 4) + h) * DK + dk) * SEQL + l] = val;
            } else if (MODE == 1) {
                int l = t >> 1, b = t & 1, h = d >> 6, dk = d & 63;
                out[(((b << 4) + h) * SEQL + l) * DK + dk] = val;
            } else {
                out[t * DMODEL + d] = val;
            }
        }
    }
}

// ---------------------------------------------------------------------------
// Flash attention: one block = 128 query rows for one (b,h).
// Q/K live in smem transposed [dk][l]/[dk][s]; V natural [s][dk]; P [s][l].
// All smem compute loads are contiguous LDS.128 (conflict-free).
// ---------------------------------------------------------------------------
__global__ void __launch_bounds__(256, 1) flash_k(const float* __restrict__ qT,
                                                  const float* __restrict__ kT,
                                                  const float* __restrict__ v,
                                                  float* __restrict__ outm)
{
    extern __shared__ float sm[];
    float* QsT = sm;                    // [64][132]  (dk, l_local)
    float* KsT = sm + 64*132;           // [64][132]  (dk, s_local)
    float* Vs  = KsT + 64*132;          // [128][68]  (s_local, dk)
    float* Ps  = Vs + 128*68;           // [128][132] (s_local, l_local)

    const int tid = threadIdx.x;
    const int ty = tid >> 4;
    const int tx = tid & 15;
    const int bh = blockIdx.y;
    const int l0 = blockIdx.x * 128;

    const float* qb = qT + bh * DK * SEQL;
    const float* kb = kT + bh * DK * SEQL;
    const float* vb = v  + bh * SEQL * DK;

    // Load Q tile once: 64 dk-rows x 128 l
    #pragma unroll
    for (int i = 0; i < 8; i++) {
        int f  = tid + i * 256;
        int dk = f >> 5;
        int l4 = (f & 31) << 2;
        *(float4*)&QsT[dk*132 + l4] = *(const float4*)(qb + dk*SEQL + l0 + l4);
    }

    float o[8][4];
    float mrow[8], lrow[8];
    #pragma unroll
    for (int r = 0; r < 8; r++) {
        mrow[r] = -1e30f; lrow[r] = 0.f;
        #pragma unroll
        for (int c = 0; c < 4; c++) o[r][c] = 0.f;
    }

    for (int s0 = 0; s0 < SEQL; s0 += 128) {
        // Load K chunk (transposed layout in global already) and V chunk
        #pragma unroll
        for (int i = 0; i < 8; i++) {
            int f  = tid + i * 256;
            int dk = f >> 5;
            int s4 = (f & 31) << 2;
            *(float4*)&KsT[dk*132 + s4] = *(const float4*)(kb + dk*SEQL + s0 + s4);
        }
        #pragma unroll
        for (int i = 0; i < 8; i++) {
            int f  = tid + i * 256;
            int sl = f >> 4;
            int d4 = (f & 15) << 2;
            *(float4*)&Vs[sl*68 + d4] = *(const float4*)(vb + (s0 + sl)*DK + d4);
        }
        __syncthreads();

        // Scores: 128x128 tile, contract over dk=64
        float sacc[8][8];
        #pragma unroll
        for (int r = 0; r < 8; r++)
            #pragma unroll
            for (int c = 0; c < 8; c++) sacc[r][c] = 0.f;

        #pragma unroll 4
        for (int kk = 0; kk < 64; kk++) {
            float4 q0 = *(const float4*)&QsT[kk*132 + 4*ty];
            float4 q1 = *(const float4*)&QsT[kk*132 + 64 + 4*ty];
            float4 k0 = *(const float4*)&KsT[kk*132 + 4*tx];
            float4 k1 = *(const float4*)&KsT[kk*132 + 64 + 4*tx];
            float qv[8] = {q0.x,q0.y,q0.z,q0.w,q1.x,q1.y,q1.z,q1.w};
            float kv[8] = {k0.x,k0.y,k0.z,k0.w,k1.x,k1.y,k1.z,k1.w};
            #pragma unroll
            for (int r = 0; r < 8; r++)
                #pragma unroll
                for (int c = 0; c < 8; c++)
                    sacc[r][c] += qv[r] * kv[c];
        }

        // Online softmax (rows shared by the 16 lanes of each half-warp)
        #pragma unroll
        for (int r = 0; r < 8; r++) {
            float mx = sacc[r][0];
            #pragma unroll
            for (int c = 1; c < 8; c++) mx = fmaxf(mx, sacc[r][c]);
            mx = fmaxf(mx, __shfl_xor_sync(0xffffffffu, mx, 1));
            mx = fmaxf(mx, __shfl_xor_sync(0xffffffffu, mx, 2));
            mx = fmaxf(mx, __shfl_xor_sync(0xffffffffu, mx, 4));
            mx = fmaxf(mx, __shfl_xor_sync(0xffffffffu, mx, 8));
            float mn = fmaxf(mrow[r], mx);
            float a  = __expf(mrow[r] - mn);
            mrow[r] = mn;
            float ls = 0.f;
            #pragma unroll
            for (int c = 0; c < 8; c++) {
                float p = __expf(sacc[r][c] - mn);
                sacc[r][c] = p;
                ls += p;
            }
            ls += __shfl_xor_sync(0xffffffffu, ls, 1);
            ls += __shfl_xor_sync(0xffffffffu, ls, 2);
            ls += __shfl_xor_sync(0xffffffffu, ls, 4);
            ls += __shfl_xor_sync(0xffffffffu, ls, 8);
            lrow[r] = lrow[r] * a + ls;
            #pragma unroll
            for (int c = 0; c < 4; c++) o[r][c] *= a;
        }

        // Stage P transposed: Ps[s_local][l_local]
        #pragma unroll
        for (int c = 0; c < 8; c++) {
            int sc = (c < 4) ? 4*tx + c : 60 + 4*tx + c;
            #pragma unroll
            for (int r = 0; r < 8; r++) {
                int lr = (r < 4) ? 4*ty + r : 60 + 4*ty + r;
                Ps[sc*132 + lr] = sacc[r][c];
            }
        }
        __syncthreads();

        // O += P @ V  (contract over s=128), O is 128 x 64
        #pragma unroll 4
        for (int s = 0; s < 128; s++) {
            float4 p0 = *(const float4*)&Ps[s*132 + 4*ty];
            float4 p1 = *(const float4*)&Ps[s*132 + 64 + 4*ty];
            float4 vv = *(const float4*)&Vs[s*68 + 4*tx];
            float pv[8] = {p0.x,p0.y,p0.z,p0.w,p1.x,p1.y,p1.z,p1.w};
            float vr[4] = {vv.x,vv.y,vv.z,vv.w};
            #pragma unroll
            for (int r = 0; r < 8; r++)
                #pragma unroll
                for (int c = 0; c < 4; c++)
                    o[r][c] += pv[r] * vr[c];
        }
        __syncthreads();   // protect KsT/Vs/Ps before next chunk overwrites
    }

    // Write merged-head layout: attn[(l*B + b)*D + h*64 + dk]
    const int b = bh >> 4, h = bh & 15;
    #pragma unroll
    for (int r = 0; r < 8; r++) {
        int l = l0 + ((r < 4) ? 4*ty + r : 60 + 4*ty + r);
        float inv = 1.f / lrow[r];
        float4 ov = make_float4(o[r][0]*inv, o[r][1]*inv, o[r][2]*inv, o[r][3]*inv);
        *(float4*)(outm + (l * BATCH + b) * DMODEL + h * DK + 4*tx) = ov;
    }
}

// ---------------------------------------------------------------------------
extern "C" void kernel_launch(void* const* d_in, const int* in_sizes, int n_in,
                              void* d_out, int out_size)
{
    const float* query = (const float*)d_in[0];
    const float* key   = (const float*)d_in[1];
    const float* value = (const float*)d_in[2];
    const float* WQ  = (const float*)d_in[3];
    const float* WQb = (const float*)d_in[4];
    const float* WK  = (const float*)d_in[5];
    const float* WKb = (const float*)d_in[6];
    const float* WV  = (const float*)d_in[7];
    const float* WVb = (const float*)d_in[8];
    const float* WO  = (const float*)d_in[9];
    const float* WOb = (const float*)d_in[10];
    float* out = (float*)d_out;

    float *qT, *kT, *vN, *attn;
    cudaGetSymbolAddress((void**)&qT,   g_qT);
    cudaGetSymbolAddress((void**)&kT,   g_kT);
    cudaGetSymbolAddress((void**)&vN,   g_v);
    cudaGetSymbolAddress((void**)&attn, g_attn);

    const int flash_smem = (64*132 + 64*132 + 128*68 + 128*132) * 4;  // 169984 B
    cudaFuncSetAttribute(flash_k, cudaFuncAttributeMaxDynamicSharedMemorySize, flash_smem);

    dim3 gblk(256);
    dim3 ggrid(DMODEL/128, NT/128);   // (8, 32)

    gemm_k<0><<<ggrid, gblk>>>(query, WQ, WQb, qT, QSCALE);  // Q (scaled)
    gemm_k<0><<<ggrid, gblk>>>(key,   WK, WKb, kT, 1.0f);    // K
    gemm_k<1><<<ggrid, gblk>>>(value, WV, WVb, vN, 1.0f);    // V

    flash_k<<<dim3(SEQL/128, BH), 256, flash_smem>>>(qT, kT, vN, attn);

    gemm_k<2><<<ggrid, gblk>>>(attn, WO, WOb, out, 1.0f);    // output proj
}

// round 7
// speedup vs baseline: 3.1190x; 3.1190x over previous
#include <cuda_runtime.h>

#define SEQL   2048
#define BATCH  2
#define DMODEL 1024
#define NHEAD  16
#define DK     64
#define NT     (SEQL*BATCH)      // 4096 token rows
#define BH     (BATCH*NHEAD)     // 32
#define QSCALE 0.125f            // DK^-0.5

// Scratch (static device globals — no runtime allocation allowed)
__device__ float g_q   [BH*SEQL*DK];   // [bh][l][dk]
__device__ float g_k   [BH*SEQL*DK];   // [bh][s][dk]
__device__ float g_v   [BH*SEQL*DK];   // [bh][s][dk]
__device__ float g_attn[NT*DMODEL];    // merged heads [t][d]

// ---------------------------------------------------------------------------
// tf32 helpers
// ---------------------------------------------------------------------------
__device__ __forceinline__ unsigned f2tf(float x) {
    unsigned r;
    asm("cvt.rna.tf32.f32 %0, %1;" : "=r"(r) : "f"(x));
    return r;
}

// D += A*B, m16n8k8 tf32 (A row-major frag, B col-major frag, f32 accum)
__device__ __forceinline__ void mma8(float c[4], const unsigned a[4],
                                     unsigned b0, unsigned b1) {
    asm("mma.sync.aligned.m16n8k8.row.col.f32.tf32.tf32.f32 "
        "{%0,%1,%2,%3},{%4,%5,%6,%7},{%8,%9},{%0,%1,%2,%3};"
        : "+f"(c[0]), "+f"(c[1]), "+f"(c[2]), "+f"(c[3])
        : "r"(a[0]), "r"(a[1]), "r"(a[2]), "r"(a[3]), "r"(b0), "r"(b1));
}

// ---------------------------------------------------------------------------
// TF32 GEMM: val[t][d] = (sum_i A[t][i]*W[d][i] + bias[d]) * scale
// Block tile 128x128, 256 threads (8 warps in 4x2 grid, warp tile 32x64).
// MODE 1: store head-split natural [bh][l/s][dk]   (Q, K, V)
// MODE 2: store plain              [t][d]          (final output)
// smem strides = 36 (36 mod 32 == 4 -> 8row x 4col fragment loads conflict-free)
// ---------------------------------------------------------------------------
template<int MODE>
__global__ void __launch_bounds__(256, 2) gemm_tc(const float* __restrict__ A,
                                                  const float* __restrict__ W,
                                                  const float* __restrict__ bias,
                                                  float* __restrict__ out,
                                                  float scale)
{
    __shared__ __align__(16) unsigned As[128*36];
    __shared__ __align__(16) unsigned Ws[128*36];

    const int tid  = threadIdx.x;
    const int lane = tid & 31;
    const int w    = tid >> 5;
    const int wm   = w >> 1;        // 0..3  -> m offset 32*wm
    const int wn   = w & 1;         // 0..1  -> n offset 64*wn
    const int t0   = blockIdx.y * 128;
    const int d0   = blockIdx.x * 128;

    float acc[2][8][4] = {};

    for (int kc = 0; kc < DMODEL; kc += 32) {
        // Load A + W 128x32 tiles, convert to tf32, store to smem
        #pragma unroll
        for (int i = 0; i < 4; i++) {
            int f  = tid + i * 256;      // 0..1023 float4 slots
            int r  = f >> 3;
            int c4 = (f & 7) << 2;
            float4 av = *(const float4*)(A + (t0 + r) * DMODEL + kc + c4);
            *(uint4*)&As[r*36 + c4] =
                make_uint4(f2tf(av.x), f2tf(av.y), f2tf(av.z), f2tf(av.w));
            float4 wv = *(const float4*)(W + (d0 + r) * DMODEL + kc + c4);
            *(uint4*)&Ws[r*36 + c4] =
                make_uint4(f2tf(wv.x), f2tf(wv.y), f2tf(wv.z), f2tf(wv.w));
        }
        __syncthreads();

        #pragma unroll
        for (int k0 = 0; k0 < 32; k0 += 8) {
            unsigned a[2][4];
            #pragma unroll
            for (int mt = 0; mt < 2; mt++) {
                int rb = (32*wm + 16*mt + (lane >> 2)) * 36 + k0 + (lane & 3);
                a[mt][0] = As[rb];
                a[mt][1] = As[rb + 8*36];
                a[mt][2] = As[rb + 4];
                a[mt][3] = As[rb + 8*36 + 4];
            }
            #pragma unroll
            for (int nt = 0; nt < 8; nt++) {
                int nb = (64*wn + 8*nt + (lane >> 2)) * 36 + k0 + (lane & 3);
                unsigned b0 = Ws[nb], b1 = Ws[nb + 4];
                mma8(acc[0][nt], a[0], b0, b1);
                mma8(acc[1][nt], a[1], b0, b1);
            }
        }
        __syncthreads();
    }

    // Epilogue: c0:(r,c) c1:(r,c+1) c2:(r+8,c) c3:(r+8,c+1)
    #pragma unroll
    for (int mt = 0; mt < 2; mt++) {
        #pragma unroll
        for (int nt = 0; nt < 8; nt++) {
            int row = t0 + 32*wm + 16*mt + (lane >> 2);
            int col = d0 + 64*wn + 8*nt + 2*(lane & 3);
            float bv0 = bias[col], bv1 = bias[col + 1];
            float v00 = (acc[mt][nt][0] + bv0) * scale;
            float v01 = (acc[mt][nt][1] + bv1) * scale;
            float v10 = (acc[mt][nt][2] + bv0) * scale;
            float v11 = (acc[mt][nt][3] + bv1) * scale;
            if (MODE == 1) {
                // t = l*B + b ; d -> (h, dk); out[((b*16+h)*SEQL + l)*64 + dk]
                int l0_ = row >> 1, b0_ = row & 1;
                int h = col >> 6, dk = col & 63;
                long i0 = (((long)(b0_*NHEAD + h))*SEQL + l0_)*DK + dk;
                *(float2*)&out[i0] = make_float2(v00, v01);
                int l1_ = (row + 8) >> 1, b1_ = (row + 8) & 1;
                long i1 = (((long)(b1_*NHEAD + h))*SEQL + l1_)*DK + dk;
                *(float2*)&out[i1] = make_float2(v10, v11);
            } else {
                *(float2*)&out[(long)row*DMODEL + col]     = make_float2(v00, v01);
                *(float2*)&out[(long)(row+8)*DMODEL + col] = make_float2(v10, v11);
            }
        }
    }
}

// ---------------------------------------------------------------------------
// TF32 flash attention. One block = 128 query rows for one (b,h).
// 8 warps; warp w owns query rows [16w, 16w+16) -> softmax rows are
// warp-local (shuffle-only reductions). P staged through warp-private smem.
// smem strides: Qs/Ks 68, Vs 72, Ps 132 (conflict-free fragment patterns).
// ---------------------------------------------------------------------------
__global__ void __launch_bounds__(256, 1) flash_tc(const float* __restrict__ q,
                                                   const float* __restrict__ k,
                                                   const float* __restrict__ v,
                                                   float* __restrict__ outm)
{
    extern __shared__ unsigned sm[];
    unsigned* Qs = sm;                  // [128][68]
    unsigned* Ks = Qs + 128*68;         // [128][68]
    unsigned* Vs = Ks + 128*68;         // [128][72]
    unsigned* Ps = Vs + 128*72;         // [128][132]

    const int tid  = threadIdx.x;
    const int lane = tid & 31;
    const int w    = tid >> 5;
    const int bh   = blockIdx.y;
    const int lblk = blockIdx.x * 128;

    const float* qb = q + ((long)bh * SEQL + lblk) * DK;
    const float* kb = k + (long)bh * SEQL * DK;
    const float* vb = v + (long)bh * SEQL * DK;

    // Load Q tile once (128 x 64), tf32-convert
    #pragma unroll
    for (int i = 0; i < 8; i++) {
        int f  = tid + i * 256;          // 0..2047 float4 slots
        int r  = f >> 4;
        int c4 = (f & 15) << 2;
        float4 t4 = *(const float4*)(qb + r*DK + c4);
        *(uint4*)&Qs[r*68 + c4] =
            make_uint4(f2tf(t4.x), f2tf(t4.y), f2tf(t4.z), f2tf(t4.w));
    }

    float o[8][4] = {};
    float mr0 = -1e30f, mr1 = -1e30f;    // running max, rows (lane>>2) and +8
    float lr0 = 0.f,    lr1 = 0.f;       // running sum

    for (int s0 = 0; s0 < SEQL; s0 += 128) {
        // Load K, V chunk
        #pragma unroll
        for (int i = 0; i < 8; i++) {
            int f  = tid + i * 256;
            int r  = f >> 4;
            int c4 = (f & 15) << 2;
            float4 kt = *(const float4*)(kb + (long)(s0 + r)*DK + c4);
            *(uint4*)&Ks[r*68 + c4] =
                make_uint4(f2tf(kt.x), f2tf(kt.y), f2tf(kt.z), f2tf(kt.w));
            float4 vt = *(const float4*)(vb + (long)(s0 + r)*DK + c4);
            *(uint4*)&Vs[r*72 + c4] =
                make_uint4(f2tf(vt.x), f2tf(vt.y), f2tf(vt.z), f2tf(vt.w));
        }
        __syncthreads();

        // S = Q * K^T : warp tile 16 x 128, contract dk=64
        float s[16][4] = {};
        #pragma unroll
        for (int k0 = 0; k0 < 64; k0 += 8) {
            unsigned a[4];
            int rb = (16*w + (lane >> 2)) * 68 + k0 + (lane & 3);
            a[0] = Qs[rb];
            a[1] = Qs[rb + 8*68];
            a[2] = Qs[rb + 4];
            a[3] = Qs[rb + 8*68 + 4];
            #pragma unroll
            for (int nt = 0; nt < 16; nt++) {
                int nb = (8*nt + (lane >> 2)) * 68 + k0 + (lane & 3);
                mma8(s[nt], a, Ks[nb], Ks[nb + 4]);
            }
        }

        // Online softmax: thread's rows = lane>>2 and lane>>2 + 8.
        // Row values spread over quad lanes (lane&3) -> shfl_xor 1,2.
        float mx0 = -1e30f, mx1 = -1e30f;
        #pragma unroll
        for (int nt = 0; nt < 16; nt++) {
            mx0 = fmaxf(mx0, fmaxf(s[nt][0], s[nt][1]));
            mx1 = fmaxf(mx1, fmaxf(s[nt][2], s[nt][3]));
        }
        mx0 = fmaxf(mx0, __shfl_xor_sync(0xffffffffu, mx0, 1));
        mx0 = fmaxf(mx0, __shfl_xor_sync(0xffffffffu, mx0, 2));
        mx1 = fmaxf(mx1, __shfl_xor_sync(0xffffffffu, mx1, 1));
        mx1 = fmaxf(mx1, __shfl_xor_sync(0xffffffffu, mx1, 2));
        float nm0 = fmaxf(mr0, mx0), nm1 = fmaxf(mr1, mx1);
        float al0 = __expf(mr0 - nm0), al1 = __expf(mr1 - nm1);
        mr0 = nm0; mr1 = nm1;
        float sum0 = 0.f, sum1 = 0.f;
        #pragma unroll
        for (int nt = 0; nt < 16; nt++) {
            s[nt][0] = __expf(s[nt][0] - nm0);
            s[nt][1] = __expf(s[nt][1] - nm0);
            s[nt][2] = __expf(s[nt][2] - nm1);
            s[nt][3] = __expf(s[nt][3] - nm1);
            sum0 += s[nt][0] + s[nt][1];
            sum1 += s[nt][2] + s[nt][3];
        }
        sum0 += __shfl_xor_sync(0xffffffffu, sum0, 1);
        sum0 += __shfl_xor_sync(0xffffffffu, sum0, 2);
        sum1 += __shfl_xor_sync(0xffffffffu, sum1, 1);
        sum1 += __shfl_xor_sync(0xffffffffu, sum1, 2);
        lr0 = lr0 * al0 + sum0;
        lr1 = lr1 * al1 + sum1;
        #pragma unroll
        for (int nt = 0; nt < 8; nt++) {
            o[nt][0] *= al0; o[nt][1] *= al0;
            o[nt][2] *= al1; o[nt][3] *= al1;
        }

        // Stage P (tf32) into warp-private smem rows [16w, 16w+16)
        {
            int pr0 = (16*w + (lane >> 2)) * 132;
            int pr1 = pr0 + 8*132;
            #pragma unroll
            for (int nt = 0; nt < 16; nt++) {
                int pc = 8*nt + 2*(lane & 3);
                *(uint2*)&Ps[pr0 + pc] = make_uint2(f2tf(s[nt][0]), f2tf(s[nt][1]));
                *(uint2*)&Ps[pr1 + pc] = make_uint2(f2tf(s[nt][2]), f2tf(s[nt][3]));
            }
        }
        __syncwarp();

        // O += P * V : warp tile 16 x 64, contract s=128
        #pragma unroll
        for (int k0 = 0; k0 < 128; k0 += 8) {
            unsigned a[4];
            int rb = (16*w + (lane >> 2)) * 132 + k0 + (lane & 3);
            a[0] = Ps[rb];
            a[1] = Ps[rb + 8*132];
            a[2] = Ps[rb + 4];
            a[3] = Ps[rb + 8*132 + 4];
            #pragma unroll
            for (int nt = 0; nt < 8; nt++) {
                int nb = (k0 + (lane & 3)) * 72 + 8*nt + (lane >> 2);
                mma8(o[nt], a, Vs[nb], Vs[nb + 4*72]);
            }
        }
        __syncthreads();   // protect Ks/Vs before next chunk overwrites
    }

    // Epilogue: merged heads attn[(l*B + b)*D + h*64 + dk]
    const int b = bh >> 4, h = bh & 15;
    float inv0 = 1.f / lr0, inv1 = 1.f / lr1;
    int lrow = lblk + 16*w + (lane >> 2);
    #pragma unroll
    for (int nt = 0; nt < 8; nt++) {
        int d = h*DK + 8*nt + 2*(lane & 3);
        *(float2*)&outm[((long)lrow*BATCH + b)*DMODEL + d] =
            make_float2(o[nt][0]*inv0, o[nt][1]*inv0);
        *(float2*)&outm[((long)(lrow+8)*BATCH + b)*DMODEL + d] =
            make_float2(o[nt][2]*inv1, o[nt][3]*inv1);
    }
}

// ---------------------------------------------------------------------------
extern "C" void kernel_launch(void* const* d_in, const int* in_sizes, int n_in,
                              void* d_out, int out_size)
{
    const float* query = (const float*)d_in[0];
    const float* key   = (const float*)d_in[1];
    const float* value = (const float*)d_in[2];
    const float* WQ  = (const float*)d_in[3];
    const float* WQb = (const float*)d_in[4];
    const float* WK  = (const float*)d_in[5];
    const float* WKb = (const float*)d_in[6];
    const float* WV  = (const float*)d_in[7];
    const float* WVb = (const float*)d_in[8];
    const float* WO  = (const float*)d_in[9];
    const float* WOb = (const float*)d_in[10];
    float* out = (float*)d_out;

    float *qN, *kN, *vN, *attn;
    cudaGetSymbolAddress((void**)&qN,   g_q);
    cudaGetSymbolAddress((void**)&kN,   g_k);
    cudaGetSymbolAddress((void**)&vN,   g_v);
    cudaGetSymbolAddress((void**)&attn, g_attn);

    const int flash_smem = 128*(68 + 68 + 72 + 132) * 4;   // 174080 B
    cudaFuncSetAttribute(flash_tc, cudaFuncAttributeMaxDynamicSharedMemorySize,
                         flash_smem);

    dim3 blk(256);
    dim3 ggrid(DMODEL/128, NT/128);   // (8, 32)

    gemm_tc<1><<<ggrid, blk>>>(query, WQ, WQb, qN, QSCALE);  // Q (scaled)
    gemm_tc<1><<<ggrid, blk>>>(key,   WK, WKb, kN, 1.0f);    // K
    gemm_tc<1><<<ggrid, blk>>>(value, WV, WVb, vN, 1.0f);    // V

    flash_tc<<<dim3(SEQL/128, BH), blk, flash_smem>>>(qN, kN, vN, attn);

    gemm_tc<2><<<ggrid, blk>>>(attn, WO, WOb, out, 1.0f);    // output proj
}

// round 10
// speedup vs baseline: 3.4937x; 1.1201x over previous
#include <cuda_runtime.h>

#define SEQL   2048
#define BATCH  2
#define DMODEL 1024
#define NHEAD  16
#define DK     64
#define NT     (SEQL*BATCH)      // 4096 token rows
#define BH     (BATCH*NHEAD)     // 32
#define QSCALE 0.125f            // DK^-0.5

// Scratch (static device globals — no runtime allocation allowed)
__device__ float g_q   [BH*SEQL*DK];   // [bh][l][dk]
__device__ float g_k   [BH*SEQL*DK];   // [bh][s][dk]
__device__ float g_v   [BH*SEQL*DK];   // [bh][s][dk]
__device__ float g_attn[NT*DMODEL];    // merged heads [t][d]

// ---------------------------------------------------------------------------
// tf32 helpers
// ---------------------------------------------------------------------------
__device__ __forceinline__ unsigned f2tf(float x) {
    unsigned r;
    asm("cvt.rna.tf32.f32 %0, %1;" : "=r"(r) : "f"(x));
    return r;
}

// D += A*B, m16n8k8 tf32 (A row-major frag, B col-major frag, f32 accum)
__device__ __forceinline__ void mma8(float c[4], const unsigned a[4],
                                     unsigned b0, unsigned b1) {
    asm("mma.sync.aligned.m16n8k8.row.col.f32.tf32.tf32.f32 "
        "{%0,%1,%2,%3},{%4,%5,%6,%7},{%8,%9},{%0,%1,%2,%3};"
        : "+f"(c[0]), "+f"(c[1]), "+f"(c[2]), "+f"(c[3])
        : "r"(a[0]), "r"(a[1]), "r"(a[2]), "r"(a[3]), "r"(b0), "r"(b1));
}

// ---------------------------------------------------------------------------
// TF32 GEMM body: val[t][d] = (sum_i A[t][i]*W[d][i] + bias[d]) * scale
// Block tile 128x128, 256 threads (8 warps in 4x2 grid, warp tile 32x64).
// MODE 1: store head-split natural [bh][l/s][dk]   (Q, K, V)
// MODE 2: store plain              [t][d]          (final output)
// ---------------------------------------------------------------------------
template<int MODE>
__device__ __forceinline__ void gemm_body(const float* __restrict__ A,
                                          const float* __restrict__ W,
                                          const float* __restrict__ bias,
                                          float* __restrict__ out,
                                          float scale)
{
    __shared__ __align__(16) unsigned As[128*36];
    __shared__ __align__(16) unsigned Ws[128*36];

    const int tid  = threadIdx.x;
    const int lane = tid & 31;
    const int w    = tid >> 5;
    const int wm   = w >> 1;
    const int wn   = w & 1;
    const int t0   = blockIdx.y * 128;
    const int d0   = blockIdx.x * 128;

    float acc[2][8][4] = {};

    for (int kc = 0; kc < DMODEL; kc += 32) {
        #pragma unroll
        for (int i = 0; i < 4; i++) {
            int f  = tid + i * 256;
            int r  = f >> 3;
            int c4 = (f & 7) << 2;
            float4 av = *(const float4*)(A + (t0 + r) * DMODEL + kc + c4);
            *(uint4*)&As[r*36 + c4] =
                make_uint4(f2tf(av.x), f2tf(av.y), f2tf(av.z), f2tf(av.w));
            float4 wv = *(const float4*)(W + (d0 + r) * DMODEL + kc + c4);
            *(uint4*)&Ws[r*36 + c4] =
                make_uint4(f2tf(wv.x), f2tf(wv.y), f2tf(wv.z), f2tf(wv.w));
        }
        __syncthreads();

        #pragma unroll
        for (int k0 = 0; k0 < 32; k0 += 8) {
            unsigned a[2][4];
            #pragma unroll
            for (int mt = 0; mt < 2; mt++) {
                int rb = (32*wm + 16*mt + (lane >> 2)) * 36 + k0 + (lane & 3);
                a[mt][0] = As[rb];
                a[mt][1] = As[rb + 8*36];
                a[mt][2] = As[rb + 4];
                a[mt][3] = As[rb + 8*36 + 4];
            }
            #pragma unroll
            for (int nt = 0; nt < 8; nt++) {
                int nb = (64*wn + 8*nt + (lane >> 2)) * 36 + k0 + (lane & 3);
                unsigned b0 = Ws[nb], b1 = Ws[nb + 4];
                mma8(acc[0][nt], a[0], b0, b1);
                mma8(acc[1][nt], a[1], b0, b1);
            }
        }
        __syncthreads();
    }

    #pragma unroll
    for (int mt = 0; mt < 2; mt++) {
        #pragma unroll
        for (int nt = 0; nt < 8; nt++) {
            int row = t0 + 32*wm + 16*mt + (lane >> 2);
            int col = d0 + 64*wn + 8*nt + 2*(lane & 3);
            float bv0 = bias[col], bv1 = bias[col + 1];
            float v00 = (acc[mt][nt][0] + bv0) * scale;
            float v01 = (acc[mt][nt][1] + bv1) * scale;
            float v10 = (acc[mt][nt][2] + bv0) * scale;
            float v11 = (acc[mt][nt][3] + bv1) * scale;
            if (MODE == 1) {
                int l0_ = row >> 1, b0_ = row & 1;
                int h = col >> 6, dk = col & 63;
                long i0 = (((long)(b0_*NHEAD + h))*SEQL + l0_)*DK + dk;
                *(float2*)&out[i0] = make_float2(v00, v01);
                int l1_ = (row + 8) >> 1, b1_ = (row + 8) & 1;
                long i1 = (((long)(b1_*NHEAD + h))*SEQL + l1_)*DK + dk;
                *(float2*)&out[i1] = make_float2(v10, v11);
            } else {
                *(float2*)&out[(long)row*DMODEL + col]     = make_float2(v00, v01);
                *(float2*)&out[(long)(row+8)*DMODEL + col] = make_float2(v10, v11);
            }
        }
    }
}

// Fused Q/K/V projections: blockIdx.z selects the stream.
__global__ void __launch_bounds__(256, 2) gemm_qkv(
    const float* __restrict__ Aq, const float* __restrict__ Ak,
    const float* __restrict__ Av,
    const float* __restrict__ Wq, const float* __restrict__ Wk,
    const float* __restrict__ Wv,
    const float* __restrict__ bq, const float* __restrict__ bk,
    const float* __restrict__ bv,
    float* __restrict__ oq, float* __restrict__ ok, float* __restrict__ ov)
{
    if (blockIdx.z == 0)      gemm_body<1>(Aq, Wq, bq, oq, QSCALE);
    else if (blockIdx.z == 1) gemm_body<1>(Ak, Wk, bk, ok, 1.0f);
    else                      gemm_body<1>(Av, Wv, bv, ov, 1.0f);
}

__global__ void __launch_bounds__(256, 2) gemm_o(const float* __restrict__ A,
                                                 const float* __restrict__ W,
                                                 const float* __restrict__ bias,
                                                 float* __restrict__ out)
{
    gemm_body<2>(A, W, bias, out, 1.0f);
}

// ---------------------------------------------------------------------------
// TF32 flash attention v2. One block = 256 query rows for one (b,h).
// 8 warps; warp w owns rows [32w, 32w+32) = 2 m-tiles -> every K/V b-fragment
// feeds 2 MMAs (halves smem read bytes vs v1). S processed in two 64-column
// halves to keep register state bounded; softmax rows stay warp-local.
// smem strides: Qs/Ks/Ps 68, Vs 72 (conflict-free fragment patterns).
// ---------------------------------------------------------------------------
__global__ void __launch_bounds__(256, 1) flash_tc(const float* __restrict__ q,
                                                   const float* __restrict__ k,
                                                   const float* __restrict__ v,
                                                   float* __restrict__ outm)
{
    extern __shared__ unsigned sm[];
    unsigned* Qs = sm;                  // [256][68]
    unsigned* Ks = Qs + 256*68;         // [128][68]
    unsigned* Vs = Ks + 128*68;         // [128][72]
    unsigned* Ps = Vs + 128*72;         // [256][68] (64 cols used per half)

    const int tid  = threadIdx.x;
    const int lane = tid & 31;
    const int w    = tid >> 5;
    const int bh   = blockIdx.y;
    const int lblk = blockIdx.x * 256;

    const float* qb = q + ((long)bh * SEQL + lblk) * DK;
    const float* kb = k + (long)bh * SEQL * DK;
    const float* vb = v + (long)bh * SEQL * DK;

    // Load Q tile once (256 x 64), tf32-convert
    #pragma unroll
    for (int i = 0; i < 16; i++) {
        int f  = tid + i * 256;
        int r  = f >> 4;
        int c4 = (f & 15) << 2;
        float4 t4 = *(const float4*)(qb + (long)r*DK + c4);
        *(uint4*)&Qs[r*68 + c4] =
            make_uint4(f2tf(t4.x), f2tf(t4.y), f2tf(t4.z), f2tf(t4.w));
    }

    float o[2][8][4] = {};
    float mr[2][2], lr[2][2];
    mr[0][0] = mr[0][1] = mr[1][0] = mr[1][1] = -1e30f;
    lr[0][0] = lr[0][1] = lr[1][0] = lr[1][1] = 0.f;

    for (int s0 = 0; s0 < SEQL; s0 += 128) {
        // Load K, V chunk (128 x 64 each)
        #pragma unroll
        for (int i = 0; i < 8; i++) {
            int f  = tid + i * 256;
            int r  = f >> 4;
            int c4 = (f & 15) << 2;
            float4 kt = *(const float4*)(kb + (long)(s0 + r)*DK + c4);
            *(uint4*)&Ks[r*68 + c4] =
                make_uint4(f2tf(kt.x), f2tf(kt.y), f2tf(kt.z), f2tf(kt.w));
            float4 vt = *(const float4*)(vb + (long)(s0 + r)*DK + c4);
            *(uint4*)&Vs[r*72 + c4] =
                make_uint4(f2tf(vt.x), f2tf(vt.y), f2tf(vt.z), f2tf(vt.w));
        }
        __syncthreads();

        #pragma unroll 1
        for (int hh = 0; hh < 2; hh++) {       // 64-col s-halves
            // S = Q * K_half^T : warp tile 32 x 64, contract dk=64
            float s[2][8][4] = {};
            #pragma unroll
            for (int k0 = 0; k0 < 64; k0 += 8) {
                unsigned a[2][4];
                #pragma unroll
                for (int mt = 0; mt < 2; mt++) {
                    int rb = (32*w + 16*mt + (lane >> 2)) * 68 + k0 + (lane & 3);
                    a[mt][0] = Qs[rb];
                    a[mt][1] = Qs[rb + 8*68];
                    a[mt][2] = Qs[rb + 4];
                    a[mt][3] = Qs[rb + 8*68 + 4];
                }
                #pragma unroll
                for (int nt = 0; nt < 8; nt++) {
                    int nb = (64*hh + 8*nt + (lane >> 2)) * 68 + k0 + (lane & 3);
                    unsigned b0 = Ks[nb], b1 = Ks[nb + 4];
                    mma8(s[0][nt], a[0], b0, b1);
                    mma8(s[1][nt], a[1], b0, b1);
                }
            }

            // Online softmax + P staging, per m-tile
            #pragma unroll
            for (int mt = 0; mt < 2; mt++) {
                float mx0 = -1e30f, mx1 = -1e30f;
                #pragma unroll
                for (int nt = 0; nt < 8; nt++) {
                    mx0 = fmaxf(mx0, fmaxf(s[mt][nt][0], s[mt][nt][1]));
                    mx1 = fmaxf(mx1, fmaxf(s[mt][nt][2], s[mt][nt][3]));
                }
                mx0 = fmaxf(mx0, __shfl_xor_sync(0xffffffffu, mx0, 1));
                mx0 = fmaxf(mx0, __shfl_xor_sync(0xffffffffu, mx0, 2));
                mx1 = fmaxf(mx1, __shfl_xor_sync(0xffffffffu, mx1, 1));
                mx1 = fmaxf(mx1, __shfl_xor_sync(0xffffffffu, mx1, 2));
                float nm0 = fmaxf(mr[mt][0], mx0), nm1 = fmaxf(mr[mt][1], mx1);
                float al0 = __expf(mr[mt][0] - nm0), al1 = __expf(mr[mt][1] - nm1);
                mr[mt][0] = nm0; mr[mt][1] = nm1;
                float su0 = 0.f, su1 = 0.f;
                #pragma unroll
                for (int nt = 0; nt < 8; nt++) {
                    s[mt][nt][0] = __expf(s[mt][nt][0] - nm0);
                    s[mt][nt][1] = __expf(s[mt][nt][1] - nm0);
                    s[mt][nt][2] = __expf(s[mt][nt][2] - nm1);
                    s[mt][nt][3] = __expf(s[mt][nt][3] - nm1);
                    su0 += s[mt][nt][0] + s[mt][nt][1];
                    su1 += s[mt][nt][2] + s[mt][nt][3];
                }
                su0 += __shfl_xor_sync(0xffffffffu, su0, 1);
                su0 += __shfl_xor_sync(0xffffffffu, su0, 2);
                su1 += __shfl_xor_sync(0xffffffffu, su1, 1);
                su1 += __shfl_xor_sync(0xffffffffu, su1, 2);
                lr[mt][0] = lr[mt][0] * al0 + su0;
                lr[mt][1] = lr[mt][1] * al1 + su1;
                #pragma unroll
                for (int nt = 0; nt < 8; nt++) {
                    o[mt][nt][0] *= al0; o[mt][nt][1] *= al0;
                    o[mt][nt][2] *= al1; o[mt][nt][3] *= al1;
                }
                // stage P-half (tf32) into warp-private smem rows
                int pr0 = (32*w + 16*mt + (lane >> 2)) * 68;
                int pr1 = pr0 + 8*68;
                #pragma unroll
                for (int nt = 0; nt < 8; nt++) {
                    int pc = 8*nt + 2*(lane & 3);
                    *(uint2*)&Ps[pr0 + pc] =
                        make_uint2(f2tf(s[mt][nt][0]), f2tf(s[mt][nt][1]));
                    *(uint2*)&Ps[pr1 + pc] =
                        make_uint2(f2tf(s[mt][nt][2]), f2tf(s[mt][nt][3]));
                }
            }
            __syncwarp();

            // O += P_half * V_half : warp tile 32 x 64, contract s=64
            #pragma unroll
            for (int k0 = 0; k0 < 64; k0 += 8) {
                unsigned a[2][4];
                #pragma unroll
                for (int mt = 0; mt < 2; mt++) {
                    int rb = (32*w + 16*mt + (lane >> 2)) * 68 + k0 + (lane & 3);
                    a[mt][0] = Ps[rb];
                    a[mt][1] = Ps[rb + 8*68];
                    a[mt][2] = Ps[rb + 4];
                    a[mt][3] = Ps[rb + 8*68 + 4];
                }
                #pragma unroll
                for (int nt = 0; nt < 8; nt++) {
                    int nb = (64*hh + k0 + (lane & 3)) * 72 + 8*nt + (lane >> 2);
                    unsigned b0 = Vs[nb], b1 = Vs[nb + 4*72];
                    mma8(o[0][nt], a[0], b0, b1);
                    mma8(o[1][nt], a[1], b0, b1);
                }
            }
            __syncwarp();   // Ps reads done before next half restages
        }
        __syncthreads();    // Ks/Vs consumed before next chunk overwrites
    }

    // Epilogue: merged heads attn[(l*B + b)*D + h*64 + dk]
    const int b = bh >> 4, h = bh & 15;
    #pragma unroll
    for (int mt = 0; mt < 2; mt++) {
        float inv0 = 1.f / lr[mt][0], inv1 = 1.f / lr[mt][1];
        int lrow = lblk + 32*w + 16*mt + (lane >> 2);
        #pragma unroll
        for (int nt = 0; nt < 8; nt++) {
            int d = h*DK + 8*nt + 2*(lane & 3);
            *(float2*)&outm[((long)lrow*BATCH + b)*DMODEL + d] =
                make_float2(o[mt][nt][0]*inv0, o[mt][nt][1]*inv0);
            *(float2*)&outm[((long)(lrow+8)*BATCH + b)*DMODEL + d] =
                make_float2(o[mt][nt][2]*inv1, o[mt][nt][3]*inv1);
        }
    }
}

// ---------------------------------------------------------------------------
extern "C" void kernel_launch(void* const* d_in, const int* in_sizes, int n_in,
                              void* d_out, int out_size)
{
    const float* query = (const float*)d_in[0];
    const float* key   = (const float*)d_in[1];
    const float* value = (const float*)d_in[2];
    const float* WQ  = (const float*)d_in[3];
    const float* WQb = (const float*)d_in[4];
    const float* WK  = (const float*)d_in[5];
    const float* WKb = (const float*)d_in[6];
    const float* WV  = (const float*)d_in[7];
    const float* WVb = (const float*)d_in[8];
    const float* WO  = (const float*)d_in[9];
    const float* WOb = (const float*)d_in[10];
    float* out = (float*)d_out;

    float *qN, *kN, *vN, *attn;
    cudaGetSymbolAddress((void**)&qN,   g_q);
    cudaGetSymbolAddress((void**)&kN,   g_k);
    cudaGetSymbolAddress((void**)&vN,   g_v);
    cudaGetSymbolAddress((void**)&attn, g_attn);

    const int flash_smem = (256*68 + 128*68 + 128*72 + 256*68) * 4;  // 210944 B
    cudaFuncSetAttribute(flash_tc, cudaFuncAttributeMaxDynamicSharedMemorySize,
                         flash_smem);

    dim3 blk(256);

    // Fused Q/K/V projections (z selects stream)
    gemm_qkv<<<dim3(DMODEL/128, NT/128, 3), blk>>>(
        query, key, value, WQ, WK, WV, WQb, WKb, WVb, qN, kN, vN);

    flash_tc<<<dim3(SEQL/256, BH), blk, flash_smem>>>(qN, kN, vN, attn);

    gemm_o<<<dim3(DMODEL/128, NT/128), blk>>>(attn, WO, WOb, out);
}

// round 13
// speedup vs baseline: 3.7093x; 1.0617x over previous
#include <cuda_runtime.h>

#define SEQL   2048
#define BATCH  2
#define DMODEL 1024
#define NHEAD  16
#define DK     64
#define NT     (SEQL*BATCH)      // 4096 token rows
#define BH     (BATCH*NHEAD)     // 32
#define QSCALE 0.125f            // DK^-0.5

// Scratch (static device globals — no runtime allocation allowed)
__device__ float g_q   [BH*SEQL*DK];   // [bh][l][dk]
__device__ float g_k   [BH*SEQL*DK];   // [bh][s][dk]
__device__ float g_v   [BH*SEQL*DK];   // [bh][s][dk]
__device__ float g_attn[NT*DMODEL];    // merged heads [t][d]

// ---------------------------------------------------------------------------
// tf32 helpers
// ---------------------------------------------------------------------------
__device__ __forceinline__ unsigned f2tf(float x) {
    unsigned r;
    asm("cvt.rna.tf32.f32 %0, %1;" : "=r"(r) : "f"(x));
    return r;
}

// D += A*B, m16n8k8 tf32 (A row-major frag, B col-major frag, f32 accum)
__device__ __forceinline__ void mma8(float c[4], const unsigned a[4],
                                     unsigned b0, unsigned b1) {
    asm("mma.sync.aligned.m16n8k8.row.col.f32.tf32.tf32.f32 "
        "{%0,%1,%2,%3},{%4,%5,%6,%7},{%8,%9},{%0,%1,%2,%3};"
        : "+f"(c[0]), "+f"(c[1]), "+f"(c[2]), "+f"(c[3])
        : "r"(a[0]), "r"(a[1]), "r"(a[2]), "r"(a[3]), "r"(b0), "r"(b1));
}

// ---------------------------------------------------------------------------
// TF32 GEMM v2: val[t][d] = (sum_i A[t][i]*W[d][i] + bias[d]) * scale
// Block tile 128(m) x 256(n), 256 threads, 8 warps in 2x4 grid,
// warp tile 64x64 (4 m-tiles x 8 n-tiles) -> 1.0 LDS per MMA (vs 1.5 in v1).
// Global loads software-pipelined: next k-chunk prefetched into registers
// while the MMA loop consumes the current smem chunk.
// MODE 1: store head-split natural [bh][l/s][dk]   (Q, K, V)
// MODE 2: store plain              [t][d]          (final output)
// smem stride 36 (36 mod 32 == 4 -> fragment patterns conflict-free)
// ---------------------------------------------------------------------------
template<int MODE>
__device__ __forceinline__ void gemm_body(const float* __restrict__ A,
                                          const float* __restrict__ W,
                                          const float* __restrict__ bias,
                                          float* __restrict__ out,
                                          float scale)
{
    extern __shared__ unsigned gsm[];
    unsigned* As = gsm;            // [128][36]
    unsigned* Ws = gsm + 128*36;   // [256][36]

    const int tid  = threadIdx.x;
    const int lane = tid & 31;
    const int w    = tid >> 5;
    const int wm   = w >> 2;        // 0..1 -> m offset 64*wm
    const int wn   = w & 3;         // 0..3 -> n offset 64*wn
    const int t0   = blockIdx.y * 128;
    const int d0   = blockIdx.x * 256;

    float acc[4][8][4] = {};
    float4 pa[4], pw[8];            // prefetch registers

    // prefetch-load k-chunk kc into registers
    auto ldg = [&](int kc) {
        #pragma unroll
        for (int i = 0; i < 4; i++) {
            int f = tid + i * 256;          // A: 128 rows x 8 float4
            int r = f >> 3, c4 = (f & 7) << 2;
            pa[i] = *(const float4*)(A + (long)(t0 + r) * DMODEL + kc + c4);
        }
        #pragma unroll
        for (int i = 0; i < 8; i++) {
            int f = tid + i * 256;          // W: 256 rows x 8 float4
            int r = f >> 3, c4 = (f & 7) << 2;
            pw[i] = *(const float4*)(W + (long)(d0 + r) * DMODEL + kc + c4);
        }
    };
    // convert + store staged registers into smem
    auto sts = [&]() {
        #pragma unroll
        for (int i = 0; i < 4; i++) {
            int f = tid + i * 256;
            int r = f >> 3, c4 = (f & 7) << 2;
            *(uint4*)&As[r*36 + c4] =
                make_uint4(f2tf(pa[i].x), f2tf(pa[i].y), f2tf(pa[i].z), f2tf(pa[i].w));
        }
        #pragma unroll
        for (int i = 0; i < 8; i++) {
            int f = tid + i * 256;
            int r = f >> 3, c4 = (f & 7) << 2;
            *(uint4*)&Ws[r*36 + c4] =
                make_uint4(f2tf(pw[i].x), f2tf(pw[i].y), f2tf(pw[i].z), f2tf(pw[i].w));
        }
    };
    // consume current smem chunk (32 k-steps)
    auto mma_chunk = [&]() {
        #pragma unroll
        for (int k0 = 0; k0 < 32; k0 += 8) {
            unsigned a[4][4];
            #pragma unroll
            for (int mt = 0; mt < 4; mt++) {
                int rb = (64*wm + 16*mt + (lane >> 2)) * 36 + k0 + (lane & 3);
                a[mt][0] = As[rb];
                a[mt][1] = As[rb + 8*36];
                a[mt][2] = As[rb + 4];
                a[mt][3] = As[rb + 8*36 + 4];
            }
            #pragma unroll
            for (int nt = 0; nt < 8; nt++) {
                int nb = (64*wn + 8*nt + (lane >> 2)) * 36 + k0 + (lane & 3);
                unsigned b0 = Ws[nb], b1 = Ws[nb + 4];
                #pragma unroll
                for (int mt = 0; mt < 4; mt++)
                    mma8(acc[mt][nt], a[mt], b0, b1);
            }
        }
    };

    ldg(0);
    sts();
    __syncthreads();
    for (int kc = 32; kc < DMODEL; kc += 32) {
        ldg(kc);            // prefetch next chunk (latency hidden by MMAs)
        mma_chunk();        // compute current chunk
        __syncthreads();    // all reads of smem done
        sts();              // overwrite with next chunk
        __syncthreads();    // stores visible
    }
    mma_chunk();            // final chunk

    // Epilogue: c0:(r,c) c1:(r,c+1) c2:(r+8,c) c3:(r+8,c+1)
    #pragma unroll
    for (int mt = 0; mt < 4; mt++) {
        #pragma unroll
        for (int nt = 0; nt < 8; nt++) {
            int row = t0 + 64*wm + 16*mt + (lane >> 2);
            int col = d0 + 64*wn + 8*nt + 2*(lane & 3);
            float bv0 = bias[col], bv1 = bias[col + 1];
            float v00 = (acc[mt][nt][0] + bv0) * scale;
            float v01 = (acc[mt][nt][1] + bv1) * scale;
            float v10 = (acc[mt][nt][2] + bv0) * scale;
            float v11 = (acc[mt][nt][3] + bv1) * scale;
            if (MODE == 1) {
                int l0_ = row >> 1, b0_ = row & 1;
                int h = col >> 6, dk = col & 63;
                long i0 = (((long)(b0_*NHEAD + h))*SEQL + l0_)*DK + dk;
                *(float2*)&out[i0] = make_float2(v00, v01);
                int l1_ = (row + 8) >> 1, b1_ = (row + 8) & 1;
                long i1 = (((long)(b1_*NHEAD + h))*SEQL + l1_)*DK + dk;
                *(float2*)&out[i1] = make_float2(v10, v11);
            } else {
                *(float2*)&out[(long)row*DMODEL + col]     = make_float2(v00, v01);
                *(float2*)&out[(long)(row+8)*DMODEL + col] = make_float2(v10, v11);
            }
        }
    }
}

// Fused Q/K/V projections: blockIdx.z selects the stream.
__global__ void __launch_bounds__(256, 1) gemm_qkv(
    const float* __restrict__ Aq, const float* __restrict__ Ak,
    const float* __restrict__ Av,
    const float* __restrict__ Wq, const float* __restrict__ Wk,
    const float* __restrict__ Wv,
    const float* __restrict__ bq, const float* __restrict__ bk,
    const float* __restrict__ bv,
    float* __restrict__ oq, float* __restrict__ ok, float* __restrict__ ov)
{
    if (blockIdx.z == 0)      gemm_body<1>(Aq, Wq, bq, oq, QSCALE);
    else if (blockIdx.z == 1) gemm_body<1>(Ak, Wk, bk, ok, 1.0f);
    else                      gemm_body<1>(Av, Wv, bv, ov, 1.0f);
}

__global__ void __launch_bounds__(256, 1) gemm_o(const float* __restrict__ A,
                                                 const float* __restrict__ W,
                                                 const float* __restrict__ bias,
                                                 float* __restrict__ out)
{
    gemm_body<2>(A, W, bias, out, 1.0f);
}

// ---------------------------------------------------------------------------
// TF32 flash attention v2 (unchanged from round 9). One block = 256 query
// rows for one (b,h). 8 warps; warp w owns rows [32w, 32w+32) = 2 m-tiles.
// ---------------------------------------------------------------------------
__global__ void __launch_bounds__(256, 1) flash_tc(const float* __restrict__ q,
                                                   const float* __restrict__ k,
                                                   const float* __restrict__ v,
                                                   float* __restrict__ outm)
{
    extern __shared__ unsigned sm[];
    unsigned* Qs = sm;                  // [256][68]
    unsigned* Ks = Qs + 256*68;         // [128][68]
    unsigned* Vs = Ks + 128*68;         // [128][72]
    unsigned* Ps = Vs + 128*72;         // [256][68] (64 cols used per half)

    const int tid  = threadIdx.x;
    const int lane = tid & 31;
    const int w    = tid >> 5;
    const int bh   = blockIdx.y;
    const int lblk = blockIdx.x * 256;

    const float* qb = q + ((long)bh * SEQL + lblk) * DK;
    const float* kb = k + (long)bh * SEQL * DK;
    const float* vb = v + (long)bh * SEQL * DK;

    // Load Q tile once (256 x 64), tf32-convert
    #pragma unroll
    for (int i = 0; i < 16; i++) {
        int f  = tid + i * 256;
        int r  = f >> 4;
        int c4 = (f & 15) << 2;
        float4 t4 = *(const float4*)(qb + (long)r*DK + c4);
        *(uint4*)&Qs[r*68 + c4] =
            make_uint4(f2tf(t4.x), f2tf(t4.y), f2tf(t4.z), f2tf(t4.w));
    }

    float o[2][8][4] = {};
    float mr[2][2], lr[2][2];
    mr[0][0] = mr[0][1] = mr[1][0] = mr[1][1] = -1e30f;
    lr[0][0] = lr[0][1] = lr[1][0] = lr[1][1] = 0.f;

    for (int s0 = 0; s0 < SEQL; s0 += 128) {
        // Load K, V chunk (128 x 64 each)
        #pragma unroll
        for (int i = 0; i < 8; i++) {
            int f  = tid + i * 256;
            int r  = f >> 4;
            int c4 = (f & 15) << 2;
            float4 kt = *(const float4*)(kb + (long)(s0 + r)*DK + c4);
            *(uint4*)&Ks[r*68 + c4] =
                make_uint4(f2tf(kt.x), f2tf(kt.y), f2tf(kt.z), f2tf(kt.w));
            float4 vt = *(const float4*)(vb + (long)(s0 + r)*DK + c4);
            *(uint4*)&Vs[r*72 + c4] =
                make_uint4(f2tf(vt.x), f2tf(vt.y), f2tf(vt.z), f2tf(vt.w));
        }
        __syncthreads();

        #pragma unroll 1
        for (int hh = 0; hh < 2; hh++) {       // 64-col s-halves
            // S = Q * K_half^T : warp tile 32 x 64, contract dk=64
            float s[2][8][4] = {};
            #pragma unroll
            for (int k0 = 0; k0 < 64; k0 += 8) {
                unsigned a[2][4];
                #pragma unroll
                for (int mt = 0; mt < 2; mt++) {
                    int rb = (32*w + 16*mt + (lane >> 2)) * 68 + k0 + (lane & 3);
                    a[mt][0] = Qs[rb];
                    a[mt][1] = Qs[rb + 8*68];
                    a[mt][2] = Qs[rb + 4];
                    a[mt][3] = Qs[rb + 8*68 + 4];
                }
                #pragma unroll
                for (int nt = 0; nt < 8; nt++) {
                    int nb = (64*hh + 8*nt + (lane >> 2)) * 68 + k0 + (lane & 3);
                    unsigned b0 = Ks[nb], b1 = Ks[nb + 4];
                    mma8(s[0][nt], a[0], b0, b1);
                    mma8(s[1][nt], a[1], b0, b1);
                }
            }

            // Online softmax + P staging, per m-tile
            #pragma unroll
            for (int mt = 0; mt < 2; mt++) {
                float mx0 = -1e30f, mx1 = -1e30f;
                #pragma unroll
                for (int nt = 0; nt < 8; nt++) {
                    mx0 = fmaxf(mx0, fmaxf(s[mt][nt][0], s[mt][nt][1]));
                    mx1 = fmaxf(mx1, fmaxf(s[mt][nt][2], s[mt][nt][3]));
                }
                mx0 = fmaxf(mx0, __shfl_xor_sync(0xffffffffu, mx0, 1));
                mx0 = fmaxf(mx0, __shfl_xor_sync(0xffffffffu, mx0, 2));
                mx1 = fmaxf(mx1, __shfl_xor_sync(0xffffffffu, mx1, 1));
                mx1 = fmaxf(mx1, __shfl_xor_sync(0xffffffffu, mx1, 2));
                float nm0 = fmaxf(mr[mt][0], mx0), nm1 = fmaxf(mr[mt][1], mx1);
                float al0 = __expf(mr[mt][0] - nm0), al1 = __expf(mr[mt][1] - nm1);
                mr[mt][0] = nm0; mr[mt][1] = nm1;
                float su0 = 0.f, su1 = 0.f;
                #pragma unroll
                for (int nt = 0; nt < 8; nt++) {
                    s[mt][nt][0] = __expf(s[mt][nt][0] - nm0);
                    s[mt][nt][1] = __expf(s[mt][nt][1] - nm0);
                    s[mt][nt][2] = __expf(s[mt][nt][2] - nm1);
                    s[mt][nt][3] = __expf(s[mt][nt][3] - nm1);
                    su0 += s[mt][nt][0] + s[mt][nt][1];
                    su1 += s[mt][nt][2] + s[mt][nt][3];
                }
                su0 += __shfl_xor_sync(0xffffffffu, su0, 1);
                su0 += __shfl_xor_sync(0xffffffffu, su0, 2);
                su1 += __shfl_xor_sync(0xffffffffu, su1, 1);
                su1 += __shfl_xor_sync(0xffffffffu, su1, 2);
                lr[mt][0] = lr[mt][0] * al0 + su0;
                lr[mt][1] = lr[mt][1] * al1 + su1;
                #pragma unroll
                for (int nt = 0; nt < 8; nt++) {
                    o[mt][nt][0] *= al0; o[mt][nt][1] *= al0;
                    o[mt][nt][2] *= al1; o[mt][nt][3] *= al1;
                }
                // stage P-half (tf32) into warp-private smem rows
                int pr0 = (32*w + 16*mt + (lane >> 2)) * 68;
                int pr1 = pr0 + 8*68;
                #pragma unroll
                for (int nt = 0; nt < 8; nt++) {
                    int pc = 8*nt + 2*(lane & 3);
                    *(uint2*)&Ps[pr0 + pc] =
                        make_uint2(f2tf(s[mt][nt][0]), f2tf(s[mt][nt][1]));
                    *(uint2*)&Ps[pr1 + pc] =
                        make_uint2(f2tf(s[mt][nt][2]), f2tf(s[mt][nt][3]));
                }
            }
            __syncwarp();

            // O += P_half * V_half : warp tile 32 x 64, contract s=64
            #pragma unroll
            for (int k0 = 0; k0 < 64; k0 += 8) {
                unsigned a[2][4];
                #pragma unroll
                for (int mt = 0; mt < 2; mt++) {
                    int rb = (32*w + 16*mt + (lane >> 2)) * 68 + k0 + (lane & 3);
                    a[mt][0] = Ps[rb];
                    a[mt][1] = Ps[rb + 8*68];
                    a[mt][2] = Ps[rb + 4];
                    a[mt][3] = Ps[rb + 8*68 + 4];
                }
                #pragma unroll
                for (int nt = 0; nt < 8; nt++) {
                    int nb = (64*hh + k0 + (lane & 3)) * 72 + 8*nt + (lane >> 2);
                    unsigned b0 = Vs[nb], b1 = Vs[nb + 4*72];
                    mma8(o[0][nt], a[0], b0, b1);
                    mma8(o[1][nt], a[1], b0, b1);
                }
            }
            __syncwarp();   // Ps reads done before next half restages
        }
        __syncthreads();    // Ks/Vs consumed before next chunk overwrites
    }

    // Epilogue: merged heads attn[(l*B + b)*D + h*64 + dk]
    const int b = bh >> 4, h = bh & 15;
    #pragma unroll
    for (int mt = 0; mt < 2; mt++) {
        float inv0 = 1.f / lr[mt][0], inv1 = 1.f / lr[mt][1];
        int lrow = lblk + 32*w + 16*mt + (lane >> 2);
        #pragma unroll
        for (int nt = 0; nt < 8; nt++) {
            int d = h*DK + 8*nt + 2*(lane & 3);
            *(float2*)&outm[((long)lrow*BATCH + b)*DMODEL + d] =
                make_float2(o[mt][nt][0]*inv0, o[mt][nt][1]*inv0);
            *(float2*)&outm[((long)(lrow+8)*BATCH + b)*DMODEL + d] =
                make_float2(o[mt][nt][2]*inv1, o[mt][nt][3]*inv1);
        }
    }
}

// ---------------------------------------------------------------------------
extern "C" void kernel_launch(void* const* d_in, const int* in_sizes, int n_in,
                              void* d_out, int out_size)
{
    const float* query = (const float*)d_in[0];
    const float* key   = (const float*)d_in[1];
    const float* value = (const float*)d_in[2];
    const float* WQ  = (const float*)d_in[3];
    const float* WQb = (const float*)d_in[4];
    const float* WK  = (const float*)d_in[5];
    const float* WKb = (const float*)d_in[6];
    const float* WV  = (const float*)d_in[7];
    const float* WVb = (const float*)d_in[8];
    const float* WO  = (const float*)d_in[9];
    const float* WOb = (const float*)d_in[10];
    float* out = (float*)d_out;

    float *qN, *kN, *vN, *attn;
    cudaGetSymbolAddress((void**)&qN,   g_q);
    cudaGetSymbolAddress((void**)&kN,   g_k);
    cudaGetSymbolAddress((void**)&vN,   g_v);
    cudaGetSymbolAddress((void**)&attn, g_attn);

    const int gemm_smem  = (128*36 + 256*36) * 4;                    // 55296 B
    const int flash_smem = (256*68 + 128*68 + 128*72 + 256*68) * 4;  // 210944 B
    cudaFuncSetAttribute(gemm_qkv, cudaFuncAttributeMaxDynamicSharedMemorySize,
                         gemm_smem);
    cudaFuncSetAttribute(gemm_o, cudaFuncAttributeMaxDynamicSharedMemorySize,
                         gemm_smem);
    cudaFuncSetAttribute(flash_tc, cudaFuncAttributeMaxDynamicSharedMemorySize,
                         flash_smem);

    dim3 blk(256);

    // Fused Q/K/V projections (z selects stream); block tile 128m x 256n
    gemm_qkv<<<dim3(DMODEL/256, NT/128, 3), blk, gemm_smem>>>(
        query, key, value, WQ, WK, WV, WQb, WKb, WVb, qN, kN, vN);

    flash_tc<<<dim3(SEQL/256, BH), blk, flash_smem>>>(qN, kN, vN, attn);

    gemm_o<<<dim3(DMODEL/256, NT/128), blk, gemm_smem>>>(attn, WO, WOb, out);
}